// round 8
// baseline (speedup 1.0000x reference)
#include <cuda_runtime.h>
#include <cstdint>

// ---- problem constants ----
#define B_ 4
#define N_ 4
#define D_ 41
#define FH_ 16
#define FW_ 44
#define C_ 64
#define NX_ 240
#define NY_ 240
#define NPTS_ (B_*N_*D_*FH_*FW_)      // 461824 = 1804*256
#define NSPAT_ (NY_*NX_)              // 57600
#define NCQ_ 16                        // channel quads
#define SCRATCH_ELEMS_ (B_*NCQ_*NSPAT_*4) // 14745600

// accumulation scratch [b][cq][spatial][4]
__device__ __align__(16) float g_scratch[SCRATCH_ELEMS_];
// per-(b,n): invPostRot[9], combine[9], trans[3], post_trans[3]
__device__ float g_mats[B_*N_][24];
// frustum u coordinates (numpy linspace bits)
__device__ float g_utab[FW_];

// non-FMA 3-dot, left-assoc ascending (XLA decomposed-dot semantics)
__device__ __forceinline__ float dot3(float c0, float c1, float c2,
                                      float p0, float p1, float p2) {
    return __fadd_rn(__fadd_rn(__fmul_rn(c0, p0), __fmul_rn(c1, p1)),
                     __fmul_rn(c2, p2));
}

// f32 3x3 inverse via LU (partial pivoting) + triangular solves,
// back-substitution uses reciprocal-of-diagonal MULTIPLY (cuBLAS trsm style).
__device__ __forceinline__ void inv3x3_cublas_f32(const float a[9], float o[9]) {
    float LU[9];
    #pragma unroll
    for (int k = 0; k < 9; k++) LU[k] = a[k];
    int perm[3] = {0, 1, 2};
    #pragma unroll
    for (int k = 0; k < 2; k++) {
        int p = k;
        float best = fabsf(LU[k*3 + k]);
        #pragma unroll
        for (int i = k + 1; i < 3; i++) {
            float v = fabsf(LU[i*3 + k]);
            if (v > best) { best = v; p = i; }
        }
        if (p != k) {
            #pragma unroll
            for (int j = 0; j < 3; j++) {
                float t = LU[k*3 + j]; LU[k*3 + j] = LU[p*3 + j]; LU[p*3 + j] = t;
            }
            int t = perm[k]; perm[k] = perm[p]; perm[p] = t;
        }
        float rkk = __fdiv_rn(1.0f, LU[k*3 + k]);
        #pragma unroll
        for (int i = k + 1; i < 3; i++) {
            float l = __fmul_rn(LU[i*3 + k], rkk);
            LU[i*3 + k] = l;
            #pragma unroll
            for (int j = k + 1; j < 3; j++)
                LU[i*3 + j] = __fadd_rn(LU[i*3 + j], -__fmul_rn(l, LU[k*3 + j]));
        }
    }
    float r0 = __fdiv_rn(1.0f, LU[0]);
    float r1 = __fdiv_rn(1.0f, LU[4]);
    float r2 = __fdiv_rn(1.0f, LU[8]);
    #pragma unroll
    for (int c = 0; c < 3; c++) {
        float y0 = (perm[0] == c) ? 1.0f : 0.0f;
        float y1 = (perm[1] == c) ? 1.0f : 0.0f;
        float y2 = (perm[2] == c) ? 1.0f : 0.0f;
        y1 = __fadd_rn(y1, -__fmul_rn(LU[3], y0));
        y2 = __fadd_rn(y2, -__fmul_rn(LU[6], y0));
        y2 = __fadd_rn(y2, -__fmul_rn(LU[7], y1));
        float x2 = __fmul_rn(y2, r2);
        float x1 = __fmul_rn(__fadd_rn(y1, -__fmul_rn(LU[5], x2)), r1);
        float x0 = __fmul_rn(__fadd_rn(__fadd_rn(y0, -__fmul_rn(LU[1], x1)),
                                       -__fmul_rn(LU[2], x2)), r0);
        o[0*3 + c] = x0; o[1*3 + c] = x1; o[2*3 + c] = x2;
    }
}

// Zero scratch (L2 warm/install for the splat's REDs) + setup matrices in block 0.
__global__ void __launch_bounds__(256) zero_setup_kernel(
        const float* __restrict__ rots,
        const float* __restrict__ trans,
        const float* __restrict__ intrins,
        const float* __restrict__ post_rots,
        const float* __restrict__ post_trans) {
    int idx = blockIdx.x * 256 + threadIdx.x;
    if (idx < SCRATCH_ELEMS_/4)
        reinterpret_cast<float4*>(g_scratch)[idx] = make_float4(0.f, 0.f, 0.f, 0.f);

    if (blockIdx.x != 0) return;
    int i = threadIdx.x;
    if (i < FW_)   // numpy linspace: f64 w*step, endpoint override
        g_utab[i] = (i == FW_-1) ? 703.0f : (float)((double)i * (703.0 / 43.0));
    if (i >= B_*N_) return;
    float A[9], iK[9], ipr[9], R[9];
    #pragma unroll
    for (int k = 0; k < 9; k++) A[k] = intrins[i*9 + k];
    inv3x3_cublas_f32(A, iK);
    #pragma unroll
    for (int k = 0; k < 9; k++) A[k] = post_rots[i*9 + k];
    inv3x3_cublas_f32(A, ipr);
    #pragma unroll
    for (int k = 0; k < 9; k++) R[k] = rots[i*9 + k];

    float* M = g_mats[i];
    #pragma unroll
    for (int k = 0; k < 9; k++) M[k] = ipr[k];
    #pragma unroll
    for (int r = 0; r < 3; r++)
        #pragma unroll
        for (int c = 0; c < 3; c++)
            M[9 + r*3 + c] = dot3(R[r*3+0], R[r*3+1], R[r*3+2],
                                  iK[c], iK[3+c], iK[6+c]);
    M[18] = trans[i*3+0];      M[19] = trans[i*3+1];      M[20] = trans[i*3+2];
    M[21] = post_trans[i*3+0]; M[22] = post_trans[i*3+1]; M[23] = post_trans[i*3+2];
}

// Two-phase splat: phase 1 = one thread per point -> base index in smem;
// phase 2 = 4 threads per point scatter 16 float4 chunks into plane layout.
__global__ void __launch_bounds__(256) splat_kernel(const float* __restrict__ x) {
    __shared__ int s_lin[256];   // b*16*NSPAT + s, or -1
    int tid = threadIdx.x;
    int p = blockIdx.x * 256 + tid;

    // ---- phase 1: geometry (bit-identical to the passing kernels) ----
    {
        int w = p % FW_;
        int t = p / FW_;
        int h = t % FH_;  t /= FH_;
        int d = t % D_;   t /= D_;
        int bn = t;                 // b*N + n
        int b  = bn >> 2;           // N_ == 4
        const float* M = g_mats[bn];

        float u   = g_utab[w];
        float v   = (float)(h * 17);            // 255/15 == 17 exact
        float dep = 4.0f + (float)d;

        float p0 = __fadd_rn(u,   -M[21]);
        float p1 = __fadd_rn(v,   -M[22]);
        float p2 = __fadd_rn(dep, -M[23]);
        float a0 = dot3(M[0], M[1], M[2], p0, p1, p2);
        float a1 = dot3(M[3], M[4], M[5], p0, p1, p2);
        float a2 = dot3(M[6], M[7], M[8], p0, p1, p2);
        float X = __fmul_rn(a0, a2);
        float Y = __fmul_rn(a1, a2);
        float Z = a2;
        float qx = __fadd_rn(dot3(M[ 9], M[10], M[11], X, Y, Z), M[18]);
        float qy = __fadd_rn(dot3(M[12], M[13], M[14], X, Y, Z), M[19]);
        float qz = __fadd_rn(dot3(M[15], M[16], M[17], X, Y, Z), M[20]);

        int vx = (int)__fdiv_rn(__fadd_rn(qx, 48.0f), 0.4f);
        int vy = (int)__fdiv_rn(__fadd_rn(qy, 48.0f), 0.4f);
        int vz = (int)__fdiv_rn(__fadd_rn(qz, 10.0f), 20.0f);
        bool kept = (vx >= 0) & (vx < NX_) & (vy >= 0) & (vy < NY_) & (vz == 0);
        s_lin[tid] = kept ? (b * (NCQ_*NSPAT_) + vy * NX_ + vx) : -1;
    }
    __syncthreads();

    // ---- phase 2: feature scatter, 4 threads per point ----
    int q = tid & 3;
    int sub = tid >> 2;           // 0..63
    #pragma unroll
    for (int j = 0; j < 4; j++) {
        int ptl = j * 64 + sub;   // local point 0..255
        int lin = s_lin[ptl];
        if (lin < 0) continue;
        const float4* src = reinterpret_cast<const float4*>(
            x + ((size_t)(blockIdx.x * 256 + ptl)) * C_);
        #pragma unroll
        for (int k = 0; k < 4; k++) {
            int cq = q + 4*k;     // 4 lanes -> contiguous 64B on the load side
            float4 f = __ldg(src + cq);
            float* dst = g_scratch + ((size_t)lin + (size_t)cq * NSPAT_) * 4;
            asm volatile("red.global.add.v4.f32 [%0], {%1, %2, %3, %4};"
                         :: "l"(dst), "f"(f.x), "f"(f.y), "f"(f.z), "f"(f.w)
                         : "memory");
        }
    }
}

// scratch [b][cq][spatial][4] -> out [b][cq*4+j][spatial].
// Pure register 4x4 transpose: no shared memory, fully coalesced both sides.
__global__ void __launch_bounds__(256) transpose_kernel(float* __restrict__ out) {
    int g = blockIdx.x * 256 + threadIdx.x;       // 0 .. 921599
    int s4    = g % (NSPAT_/4);                   // spatial group of 4
    int plane = g / (NSPAT_/4);                   // b*16 + cq, 0..63
    const float4* in4 = reinterpret_cast<const float4*>(g_scratch)
                        + (size_t)plane * NSPAT_ + (size_t)s4 * 4;
    float4 v0 = in4[0], v1 = in4[1], v2 = in4[2], v3 = in4[3];
    float4* out4 = reinterpret_cast<float4*>(out);
    size_t obase = (size_t)plane * 4 * (NSPAT_/4) + s4;   // channel c = plane*4+j
    out4[obase + 0*(NSPAT_/4)] = make_float4(v0.x, v1.x, v2.x, v3.x);
    out4[obase + 1*(NSPAT_/4)] = make_float4(v0.y, v1.y, v2.y, v3.y);
    out4[obase + 2*(NSPAT_/4)] = make_float4(v0.z, v1.z, v2.z, v3.z);
    out4[obase + 3*(NSPAT_/4)] = make_float4(v0.w, v1.w, v2.w, v3.w);
}

extern "C" void kernel_launch(void* const* d_in, const int* in_sizes, int n_in,
                              void* d_out, int out_size) {
    const float* x          = (const float*)d_in[0];
    const float* rots       = (const float*)d_in[1];
    const float* trans      = (const float*)d_in[2];
    const float* intrins    = (const float*)d_in[3];
    const float* post_rots  = (const float*)d_in[4];
    const float* post_trans = (const float*)d_in[5];
    float* out = (float*)d_out;

    zero_setup_kernel<<<(SCRATCH_ELEMS_/4 + 255)/256, 256>>>(
        rots, trans, intrins, post_rots, post_trans);
    splat_kernel<<<NPTS_/256, 256>>>(x);
    transpose_kernel<<<(B_*NCQ_*(NSPAT_/4))/256, 256>>>(out);
}

// round 10
// speedup vs baseline: 1.1984x; 1.1984x over previous
#include <cuda_runtime.h>
#include <cstdint>

// ---- problem constants ----
#define B_ 4
#define N_ 4
#define D_ 41
#define FH_ 16
#define FW_ 44
#define C_ 64
#define NX_ 240
#define NY_ 240
#define NPTS_ (B_*N_*D_*FH_*FW_)      // 461824 = 1804*256
#define NSPAT_ (NY_*NX_)              // 57600
#define SCRATCH_ELEMS_ (B_*NSPAT_*C_) // 14745600

// channel-last accumulation scratch [b][y][x][c] (256B per voxel, contiguous)
__device__ __align__(16) float g_scratch[SCRATCH_ELEMS_];
// per-(b,n): invPostRot[9], combine[9], trans[3], post_trans[3]
__device__ float g_mats[B_*N_][24];
// frustum u coordinates (numpy linspace bits)
__device__ float g_utab[FW_];

// non-FMA 3-dot, left-assoc ascending (XLA decomposed-dot semantics)
__device__ __forceinline__ float dot3(float c0, float c1, float c2,
                                      float p0, float p1, float p2) {
    return __fadd_rn(__fadd_rn(__fmul_rn(c0, p0), __fmul_rn(c1, p1)),
                     __fmul_rn(c2, p2));
}

// f32 3x3 inverse via LU (partial pivoting) + triangular solves,
// back-substitution uses reciprocal-of-diagonal MULTIPLY (cuBLAS trsm style).
__device__ __forceinline__ void inv3x3_cublas_f32(const float a[9], float o[9]) {
    float LU[9];
    #pragma unroll
    for (int k = 0; k < 9; k++) LU[k] = a[k];
    int perm[3] = {0, 1, 2};
    #pragma unroll
    for (int k = 0; k < 2; k++) {
        int p = k;
        float best = fabsf(LU[k*3 + k]);
        #pragma unroll
        for (int i = k + 1; i < 3; i++) {
            float v = fabsf(LU[i*3 + k]);
            if (v > best) { best = v; p = i; }
        }
        if (p != k) {
            #pragma unroll
            for (int j = 0; j < 3; j++) {
                float t = LU[k*3 + j]; LU[k*3 + j] = LU[p*3 + j]; LU[p*3 + j] = t;
            }
            int t = perm[k]; perm[k] = perm[p]; perm[p] = t;
        }
        float rkk = __fdiv_rn(1.0f, LU[k*3 + k]);
        #pragma unroll
        for (int i = k + 1; i < 3; i++) {
            float l = __fmul_rn(LU[i*3 + k], rkk);
            LU[i*3 + k] = l;
            #pragma unroll
            for (int j = k + 1; j < 3; j++)
                LU[i*3 + j] = __fadd_rn(LU[i*3 + j], -__fmul_rn(l, LU[k*3 + j]));
        }
    }
    float r0 = __fdiv_rn(1.0f, LU[0]);
    float r1 = __fdiv_rn(1.0f, LU[4]);
    float r2 = __fdiv_rn(1.0f, LU[8]);
    #pragma unroll
    for (int c = 0; c < 3; c++) {
        float y0 = (perm[0] == c) ? 1.0f : 0.0f;
        float y1 = (perm[1] == c) ? 1.0f : 0.0f;
        float y2 = (perm[2] == c) ? 1.0f : 0.0f;
        y1 = __fadd_rn(y1, -__fmul_rn(LU[3], y0));
        y2 = __fadd_rn(y2, -__fmul_rn(LU[6], y0));
        y2 = __fadd_rn(y2, -__fmul_rn(LU[7], y1));
        float x2 = __fmul_rn(y2, r2);
        float x1 = __fmul_rn(__fadd_rn(y1, -__fmul_rn(LU[5], x2)), r1);
        float x0 = __fmul_rn(__fadd_rn(__fadd_rn(y0, -__fmul_rn(LU[1], x1)),
                                       -__fmul_rn(LU[2], x2)), r0);
        o[0*3 + c] = x0; o[1*3 + c] = x1; o[2*3 + c] = x2;
    }
}

// Zero scratch (L2 warm/install for the splat's REDs) + setup matrices in block 0.
__global__ void __launch_bounds__(256) zero_setup_kernel(
        const float* __restrict__ rots,
        const float* __restrict__ trans,
        const float* __restrict__ intrins,
        const float* __restrict__ post_rots,
        const float* __restrict__ post_trans) {
    int idx = blockIdx.x * 256 + threadIdx.x;
    if (idx < SCRATCH_ELEMS_/4)
        reinterpret_cast<float4*>(g_scratch)[idx] = make_float4(0.f, 0.f, 0.f, 0.f);

    if (blockIdx.x != 0) return;
    int i = threadIdx.x;
    if (i < FW_)   // numpy linspace: f64 w*step, endpoint override
        g_utab[i] = (i == FW_-1) ? 703.0f : (float)((double)i * (703.0 / 43.0));
    if (i >= B_*N_) return;
    float A[9], iK[9], ipr[9], R[9];
    #pragma unroll
    for (int k = 0; k < 9; k++) A[k] = intrins[i*9 + k];
    inv3x3_cublas_f32(A, iK);
    #pragma unroll
    for (int k = 0; k < 9; k++) A[k] = post_rots[i*9 + k];
    inv3x3_cublas_f32(A, ipr);
    #pragma unroll
    for (int k = 0; k < 9; k++) R[k] = rots[i*9 + k];

    float* M = g_mats[i];
    #pragma unroll
    for (int k = 0; k < 9; k++) M[k] = ipr[k];
    #pragma unroll
    for (int r = 0; r < 3; r++)
        #pragma unroll
        for (int c = 0; c < 3; c++)
            M[9 + r*3 + c] = dot3(R[r*3+0], R[r*3+1], R[r*3+2],
                                  iK[c], iK[3+c], iK[6+c]);
    M[18] = trans[i*3+0];      M[19] = trans[i*3+1];      M[20] = trans[i*3+2];
    M[21] = post_trans[i*3+0]; M[22] = post_trans[i*3+1]; M[23] = post_trans[i*3+2];
}

// Two-phase splat: phase 1 = one thread per point -> voxel lin index in smem;
// phase 2 = 4 threads per point move 16 float4 chunks (coalesced 64B groups,
// REDs land in a contiguous 256B voxel record = 2 L2 lines per point).
__global__ void __launch_bounds__(256) splat_kernel(const float* __restrict__ x) {
    __shared__ int s_lin[256];
    int tid = threadIdx.x;
    int p = blockIdx.x * 256 + tid;

    // ---- phase 1: geometry (bit-identical to the passing kernels) ----
    {
        int w = p % FW_;
        int t = p / FW_;
        int h = t % FH_;  t /= FH_;
        int d = t % D_;   t /= D_;
        int bn = t;                 // b*N + n
        int b  = bn >> 2;           // N_ == 4
        const float* M = g_mats[bn];

        float u   = g_utab[w];
        float v   = (float)(h * 17);            // 255/15 == 17 exact
        float dep = 4.0f + (float)d;

        float p0 = __fadd_rn(u,   -M[21]);
        float p1 = __fadd_rn(v,   -M[22]);
        float p2 = __fadd_rn(dep, -M[23]);
        float a0 = dot3(M[0], M[1], M[2], p0, p1, p2);
        float a1 = dot3(M[3], M[4], M[5], p0, p1, p2);
        float a2 = dot3(M[6], M[7], M[8], p0, p1, p2);
        float X = __fmul_rn(a0, a2);
        float Y = __fmul_rn(a1, a2);
        float Z = a2;
        float qx = __fadd_rn(dot3(M[ 9], M[10], M[11], X, Y, Z), M[18]);
        float qy = __fadd_rn(dot3(M[12], M[13], M[14], X, Y, Z), M[19]);
        float qz = __fadd_rn(dot3(M[15], M[16], M[17], X, Y, Z), M[20]);

        int vx = (int)__fdiv_rn(__fadd_rn(qx, 48.0f), 0.4f);
        int vy = (int)__fdiv_rn(__fadd_rn(qy, 48.0f), 0.4f);
        int vz = (int)__fdiv_rn(__fadd_rn(qz, 10.0f), 20.0f);
        bool kept = (vx >= 0) & (vx < NX_) & (vy >= 0) & (vy < NY_) & (vz == 0);
        s_lin[tid] = kept ? (b * NSPAT_ + vy * NX_ + vx) : -1;
    }
    __syncthreads();

    // ---- phase 2: feature scatter, 4 threads per point ----
    int q = tid & 3;
    int sub = tid >> 2;           // 0..63
    #pragma unroll
    for (int j = 0; j < 4; j++) {
        int ptl = j * 64 + sub;   // local point 0..255
        int lin = s_lin[ptl];
        if (lin < 0) continue;
        const float4* src = reinterpret_cast<const float4*>(
            x + ((size_t)(blockIdx.x * 256 + ptl)) * C_);
        float* dst = g_scratch + (size_t)lin * C_;
        #pragma unroll
        for (int k = 0; k < 4; k++) {
            int chunk = q + 4*k;  // 4 lanes -> contiguous 64B
            float4 f = __ldg(src + chunk);
            asm volatile("red.global.add.v4.f32 [%0], {%1, %2, %3, %4};"
                         :: "l"(dst + 4*chunk), "f"(f.x), "f"(f.y), "f"(f.z), "f"(f.w)
                         : "memory");
        }
    }
}

// [b][s][c] -> [b][c][s]; 64 spatial x 64 channel tile, all accesses 128-bit.
// Global load (lanes: cq fastest -> 256B runs) -> 4x4 register transpose ->
// STS.128 into XOR-swizzled tile (quad = s4 ^ (cq&7): conflict-free phases)
// -> LDS.128 (c const per phase: conflict-free) -> coalesced STG.128.
__global__ void __launch_bounds__(256) transpose_kernel(float* __restrict__ out) {
    __shared__ __align__(16) float4 tile4[C_ * 16];   // 64 rows x 16 float4 = 16KB
    int b  = blockIdx.y;
    int s0 = blockIdx.x * 64;
    const float* sc = g_scratch + (size_t)b * NSPAT_ * C_;
    int t = threadIdx.x;
    int s4 = t >> 4;       // 0..15  spatial quad
    int cq = t & 15;       // 0..15  channel quad
    float4 v0 = *(reinterpret_cast<const float4*>(sc + (size_t)(s0 + s4*4 + 0) * C_) + cq);
    float4 v1 = *(reinterpret_cast<const float4*>(sc + (size_t)(s0 + s4*4 + 1) * C_) + cq);
    float4 v2 = *(reinterpret_cast<const float4*>(sc + (size_t)(s0 + s4*4 + 2) * C_) + cq);
    float4 v3 = *(reinterpret_cast<const float4*>(sc + (size_t)(s0 + s4*4 + 3) * C_) + cq);
    // 4x4 register transpose: w_j = spatials s4*4..+3 of channel cq*4+j
    float4 w0 = make_float4(v0.x, v1.x, v2.x, v3.x);
    float4 w1 = make_float4(v0.y, v1.y, v2.y, v3.y);
    float4 w2 = make_float4(v0.z, v1.z, v2.z, v3.z);
    float4 w3 = make_float4(v0.w, v1.w, v2.w, v3.w);
    int swz = s4 ^ (cq & 7);          // row>>2 == cq for all 4 stored rows
    tile4[(cq*4 + 0) * 16 + swz] = w0;
    tile4[(cq*4 + 1) * 16 + swz] = w1;
    tile4[(cq*4 + 2) * 16 + swz] = w2;
    tile4[(cq*4 + 3) * 16 + swz] = w3;
    __syncthreads();
    float* ob = out + (size_t)b * C_ * NSPAT_;
    #pragma unroll
    for (int i = 0; i < 4; i++) {
        int lin = t + i*256;      // 0..1023
        int c   = lin >> 4;       // 0..63
        int sq  = lin & 15;       // 0..15
        float4 w = tile4[c * 16 + (sq ^ ((c >> 2) & 7))];
        *reinterpret_cast<float4*>(ob + (size_t)c * NSPAT_ + s0 + sq*4) = w;
    }
}

extern "C" void kernel_launch(void* const* d_in, const int* in_sizes, int n_in,
                              void* d_out, int out_size) {
    const float* x          = (const float*)d_in[0];
    const float* rots       = (const float*)d_in[1];
    const float* trans      = (const float*)d_in[2];
    const float* intrins    = (const float*)d_in[3];
    const float* post_rots  = (const float*)d_in[4];
    const float* post_trans = (const float*)d_in[5];
    float* out = (float*)d_out;

    zero_setup_kernel<<<(SCRATCH_ELEMS_/4 + 255)/256, 256>>>(
        rots, trans, intrins, post_rots, post_trans);
    splat_kernel<<<NPTS_/256, 256>>>(x);
    transpose_kernel<<<dim3(NSPAT_/64, B_), 256>>>(out);
}

// round 11
// speedup vs baseline: 1.3109x; 1.0938x over previous
#include <cuda_runtime.h>
#include <cstdint>

// ---- problem constants ----
#define B_ 4
#define N_ 4
#define D_ 41
#define FH_ 16
#define FW_ 44
#define C_ 64
#define NPTS_ (B_*N_*D_*FH_*FW_)      // 461824 = 1804*256
#define NSPAT_ (NY_*NX_)              // 57600
#define NX_ 240
#define NY_ 240
#define SCRATCH_ELEMS_ (B_*NSPAT_*C_) // 14745600

// channel-last accumulation scratch [b][y][x][c] (256B per voxel, contiguous)
__device__ __align__(16) float g_scratch[SCRATCH_ELEMS_];
// per-(b,n): invPostRot[9], combine[9], trans[3], post_trans[3]
__device__ float g_mats[B_*N_][24];
// frustum u coordinates (numpy linspace bits)
__device__ float g_utab[FW_];

// non-FMA 3-dot, left-assoc ascending (XLA decomposed-dot semantics)
__device__ __forceinline__ float dot3(float c0, float c1, float c2,
                                      float p0, float p1, float p2) {
    return __fadd_rn(__fadd_rn(__fmul_rn(c0, p0), __fmul_rn(c1, p1)),
                     __fmul_rn(c2, p2));
}

// f32 3x3 inverse via LU (partial pivoting) + triangular solves,
// back-substitution uses reciprocal-of-diagonal MULTIPLY (cuBLAS trsm style).
__device__ __forceinline__ void inv3x3_cublas_f32(const float a[9], float o[9]) {
    float LU[9];
    #pragma unroll
    for (int k = 0; k < 9; k++) LU[k] = a[k];
    int perm[3] = {0, 1, 2};
    #pragma unroll
    for (int k = 0; k < 2; k++) {
        int p = k;
        float best = fabsf(LU[k*3 + k]);
        #pragma unroll
        for (int i = k + 1; i < 3; i++) {
            float v = fabsf(LU[i*3 + k]);
            if (v > best) { best = v; p = i; }
        }
        if (p != k) {
            #pragma unroll
            for (int j = 0; j < 3; j++) {
                float t = LU[k*3 + j]; LU[k*3 + j] = LU[p*3 + j]; LU[p*3 + j] = t;
            }
            int t = perm[k]; perm[k] = perm[p]; perm[p] = t;
        }
        float rkk = __fdiv_rn(1.0f, LU[k*3 + k]);
        #pragma unroll
        for (int i = k + 1; i < 3; i++) {
            float l = __fmul_rn(LU[i*3 + k], rkk);
            LU[i*3 + k] = l;
            #pragma unroll
            for (int j = k + 1; j < 3; j++)
                LU[i*3 + j] = __fadd_rn(LU[i*3 + j], -__fmul_rn(l, LU[k*3 + j]));
        }
    }
    float r0 = __fdiv_rn(1.0f, LU[0]);
    float r1 = __fdiv_rn(1.0f, LU[4]);
    float r2 = __fdiv_rn(1.0f, LU[8]);
    #pragma unroll
    for (int c = 0; c < 3; c++) {
        float y0 = (perm[0] == c) ? 1.0f : 0.0f;
        float y1 = (perm[1] == c) ? 1.0f : 0.0f;
        float y2 = (perm[2] == c) ? 1.0f : 0.0f;
        y1 = __fadd_rn(y1, -__fmul_rn(LU[3], y0));
        y2 = __fadd_rn(y2, -__fmul_rn(LU[6], y0));
        y2 = __fadd_rn(y2, -__fmul_rn(LU[7], y1));
        float x2 = __fmul_rn(y2, r2);
        float x1 = __fmul_rn(__fadd_rn(y1, -__fmul_rn(LU[5], x2)), r1);
        float x0 = __fmul_rn(__fadd_rn(__fadd_rn(y0, -__fmul_rn(LU[1], x1)),
                                       -__fmul_rn(LU[2], x2)), r0);
        o[0*3 + c] = x0; o[1*3 + c] = x1; o[2*3 + c] = x2;
    }
}

// Zero scratch (grid-stride, 4 float4/thread) + setup matrices in block 0.
__global__ void __launch_bounds__(256) zero_setup_kernel(
        const float* __restrict__ rots,
        const float* __restrict__ trans,
        const float* __restrict__ intrins,
        const float* __restrict__ post_rots,
        const float* __restrict__ post_trans) {
    float4* s4 = reinterpret_cast<float4*>(g_scratch);
    int base = blockIdx.x * 256 + threadIdx.x;
    const int stride = 3600 * 256;     // grid is 3600 blocks
    #pragma unroll
    for (int i = 0; i < 4; i++) {
        int idx = base + i * stride;
        s4[idx] = make_float4(0.f, 0.f, 0.f, 0.f);
    }

    if (blockIdx.x != 0) return;
    int i = threadIdx.x;
    if (i < FW_)   // numpy linspace: f64 w*step, endpoint override
        g_utab[i] = (i == FW_-1) ? 703.0f : (float)((double)i * (703.0 / 43.0));
    if (i >= B_*N_) return;
    float A[9], iK[9], ipr[9], R[9];
    #pragma unroll
    for (int k = 0; k < 9; k++) A[k] = intrins[i*9 + k];
    inv3x3_cublas_f32(A, iK);
    #pragma unroll
    for (int k = 0; k < 9; k++) A[k] = post_rots[i*9 + k];
    inv3x3_cublas_f32(A, ipr);
    #pragma unroll
    for (int k = 0; k < 9; k++) R[k] = rots[i*9 + k];

    float* M = g_mats[i];
    #pragma unroll
    for (int k = 0; k < 9; k++) M[k] = ipr[k];
    #pragma unroll
    for (int r = 0; r < 3; r++)
        #pragma unroll
        for (int c = 0; c < 3; c++)
            M[9 + r*3 + c] = dot3(R[r*3+0], R[r*3+1], R[r*3+2],
                                  iK[c], iK[3+c], iK[6+c]);
    M[18] = trans[i*3+0];      M[19] = trans[i*3+1];      M[20] = trans[i*3+2];
    M[21] = post_trans[i*3+0]; M[22] = post_trans[i*3+1]; M[23] = post_trans[i*3+2];
}

// Splat with h-group dedup.
// Threads are mapped h-fastest: q = ...((bn,d),w),h. The 16 points of a group
// (fixed b,n,d,w; h=0..15) usually land in the SAME voxel (vertical pixel axis
// maps to ego-z only). Phase 1 computes each point's lin bit-identically;
// phase 2 checks group uniformity at runtime: uniform -> pre-sum 16 features,
// 1 RED per channel-quad (16x fewer atomics); else -> per-point REDs fallback.
__global__ void __launch_bounds__(256) splat_kernel(const float* __restrict__ x) {
    __shared__ int s_lin[256];
    __shared__ int s_p[256];     // original point index (for x addressing)
    __shared__ int s_uni[16];
    int tid = threadIdx.x;
    int q = blockIdx.x * 256 + tid;

    // ---- phase 1: geometry (bit-identical arithmetic; h-fastest mapping) ----
    {
        int h = q & 15;            // FH_ == 16
        int t = q >> 4;
        int w = t % FW_;  t /= FW_;
        int d = t % D_;
        int bn = t / D_;           // b*N + n
        int b  = bn >> 2;          // N_ == 4
        s_p[tid] = ((bn * D_ + d) * FH_ + h) * FW_ + w;
        const float* M = g_mats[bn];

        float u   = g_utab[w];
        float v   = (float)(h * 17);            // 255/15 == 17 exact
        float dep = 4.0f + (float)d;

        float p0 = __fadd_rn(u,   -M[21]);
        float p1 = __fadd_rn(v,   -M[22]);
        float p2 = __fadd_rn(dep, -M[23]);
        float a0 = dot3(M[0], M[1], M[2], p0, p1, p2);
        float a1 = dot3(M[3], M[4], M[5], p0, p1, p2);
        float a2 = dot3(M[6], M[7], M[8], p0, p1, p2);
        float X = __fmul_rn(a0, a2);
        float Y = __fmul_rn(a1, a2);
        float Z = a2;
        float qx = __fadd_rn(dot3(M[ 9], M[10], M[11], X, Y, Z), M[18]);
        float qy = __fadd_rn(dot3(M[12], M[13], M[14], X, Y, Z), M[19]);
        float qz = __fadd_rn(dot3(M[15], M[16], M[17], X, Y, Z), M[20]);

        int vx = (int)__fdiv_rn(__fadd_rn(qx, 48.0f), 0.4f);
        int vy = (int)__fdiv_rn(__fadd_rn(qy, 48.0f), 0.4f);
        int vz = (int)__fdiv_rn(__fadd_rn(qz, 10.0f), 20.0f);
        bool kept = (vx >= 0) & (vx < NX_) & (vy >= 0) & (vy < NY_) & (vz == 0);
        s_lin[tid] = kept ? (b * NSPAT_ + vy * NX_ + vx) : -1;
    }
    __syncthreads();

    if ((tid & 15) == 0) {       // group-uniformity check (one thread per group)
        int g16 = tid;           // == g*16
        int l0 = s_lin[g16];
        bool uni = true;
        #pragma unroll
        for (int i = 1; i < 16; i++) uni &= (s_lin[g16 + i] == l0);
        s_uni[tid >> 4] = uni;
    }
    __syncthreads();

    // ---- phase 2: one group of 16 points per 16 threads; thread = channel quad ----
    int g  = tid >> 4;
    int cq = tid & 15;
    const float4* x4 = reinterpret_cast<const float4*>(x);
    if (s_uni[g]) {
        int lin = s_lin[g * 16];
        if (lin >= 0) {
            float4 acc = __ldg(x4 + (size_t)s_p[g*16] * 16 + cq);
            #pragma unroll
            for (int i = 1; i < 16; i++) {
                float4 f = __ldg(x4 + (size_t)s_p[g*16 + i] * 16 + cq);
                acc.x = __fadd_rn(acc.x, f.x);
                acc.y = __fadd_rn(acc.y, f.y);
                acc.z = __fadd_rn(acc.z, f.z);
                acc.w = __fadd_rn(acc.w, f.w);
            }
            float* dst = g_scratch + (size_t)lin * C_ + cq * 4;
            asm volatile("red.global.add.v4.f32 [%0], {%1, %2, %3, %4};"
                         :: "l"(dst), "f"(acc.x), "f"(acc.y), "f"(acc.z), "f"(acc.w)
                         : "memory");
        }
    } else {
        #pragma unroll 1
        for (int i = 0; i < 16; i++) {
            int lin = s_lin[g*16 + i];
            if (lin < 0) continue;
            float4 f = __ldg(x4 + (size_t)s_p[g*16 + i] * 16 + cq);
            float* dst = g_scratch + (size_t)lin * C_ + cq * 4;
            asm volatile("red.global.add.v4.f32 [%0], {%1, %2, %3, %4};"
                         :: "l"(dst), "f"(f.x), "f"(f.y), "f"(f.z), "f"(f.w)
                         : "memory");
        }
    }
}

// [b][s][c] -> [b][c][s]; 64 spatial x 64 channel tile, all accesses 128-bit.
// XOR-swizzled smem tile: conflict-free 128-bit phases both directions.
__global__ void __launch_bounds__(256) transpose_kernel(float* __restrict__ out) {
    __shared__ __align__(16) float4 tile4[C_ * 16];   // 64 rows x 16 float4 = 16KB
    int b  = blockIdx.y;
    int s0 = blockIdx.x * 64;
    const float* sc = g_scratch + (size_t)b * NSPAT_ * C_;
    int t = threadIdx.x;
    int s4 = t >> 4;       // 0..15  spatial quad
    int cq = t & 15;       // 0..15  channel quad
    float4 v0 = *(reinterpret_cast<const float4*>(sc + (size_t)(s0 + s4*4 + 0) * C_) + cq);
    float4 v1 = *(reinterpret_cast<const float4*>(sc + (size_t)(s0 + s4*4 + 1) * C_) + cq);
    float4 v2 = *(reinterpret_cast<const float4*>(sc + (size_t)(s0 + s4*4 + 2) * C_) + cq);
    float4 v3 = *(reinterpret_cast<const float4*>(sc + (size_t)(s0 + s4*4 + 3) * C_) + cq);
    float4 w0 = make_float4(v0.x, v1.x, v2.x, v3.x);
    float4 w1 = make_float4(v0.y, v1.y, v2.y, v3.y);
    float4 w2 = make_float4(v0.z, v1.z, v2.z, v3.z);
    float4 w3 = make_float4(v0.w, v1.w, v2.w, v3.w);
    int swz = s4 ^ (cq & 7);
    tile4[(cq*4 + 0) * 16 + swz] = w0;
    tile4[(cq*4 + 1) * 16 + swz] = w1;
    tile4[(cq*4 + 2) * 16 + swz] = w2;
    tile4[(cq*4 + 3) * 16 + swz] = w3;
    __syncthreads();
    float* ob = out + (size_t)b * C_ * NSPAT_;
    #pragma unroll
    for (int i = 0; i < 4; i++) {
        int lin = t + i*256;      // 0..1023
        int c   = lin >> 4;       // 0..63
        int sq  = lin & 15;       // 0..15
        float4 w = tile4[c * 16 + (sq ^ ((c >> 2) & 7))];
        *reinterpret_cast<float4*>(ob + (size_t)c * NSPAT_ + s0 + sq*4) = w;
    }
}

extern "C" void kernel_launch(void* const* d_in, const int* in_sizes, int n_in,
                              void* d_out, int out_size) {
    const float* x          = (const float*)d_in[0];
    const float* rots       = (const float*)d_in[1];
    const float* trans      = (const float*)d_in[2];
    const float* intrins    = (const float*)d_in[3];
    const float* post_rots  = (const float*)d_in[4];
    const float* post_trans = (const float*)d_in[5];
    float* out = (float*)d_out;

    zero_setup_kernel<<<3600, 256>>>(rots, trans, intrins, post_rots, post_trans);
    splat_kernel<<<NPTS_/256, 256>>>(x);
    transpose_kernel<<<dim3(NSPAT_/64, B_), 256>>>(out);
}

// round 12
// speedup vs baseline: 1.4961x; 1.1413x over previous
#include <cuda_runtime.h>
#include <cstdint>

// ---- problem constants ----
#define B_ 4
#define N_ 4
#define D_ 41
#define FH_ 16
#define FW_ 44
#define C_ 64
#define NX_ 240
#define NY_ 240
#define NPTS_ (B_*N_*D_*FH_*FW_)      // 461824 = 1804*256
#define NSPAT_ (NY_*NX_)              // 57600
#define OUT_ELEMS_ (B_*C_*NSPAT_)     // 14745600

// per-(b,n): invPostRot[9], combine[9], trans[3], post_trans[3]
__device__ float g_mats[B_*N_][24];
// frustum u coordinates (numpy linspace bits)
__device__ float g_utab[FW_];

// non-FMA 3-dot, left-assoc ascending (XLA decomposed-dot semantics)
__device__ __forceinline__ float dot3(float c0, float c1, float c2,
                                      float p0, float p1, float p2) {
    return __fadd_rn(__fadd_rn(__fmul_rn(c0, p0), __fmul_rn(c1, p1)),
                     __fmul_rn(c2, p2));
}

// f32 3x3 inverse via LU (partial pivoting) + triangular solves,
// back-substitution uses reciprocal-of-diagonal MULTIPLY (cuBLAS trsm style).
__device__ __forceinline__ void inv3x3_cublas_f32(const float a[9], float o[9]) {
    float LU[9];
    #pragma unroll
    for (int k = 0; k < 9; k++) LU[k] = a[k];
    int perm[3] = {0, 1, 2};
    #pragma unroll
    for (int k = 0; k < 2; k++) {
        int p = k;
        float best = fabsf(LU[k*3 + k]);
        #pragma unroll
        for (int i = k + 1; i < 3; i++) {
            float v = fabsf(LU[i*3 + k]);
            if (v > best) { best = v; p = i; }
        }
        if (p != k) {
            #pragma unroll
            for (int j = 0; j < 3; j++) {
                float t = LU[k*3 + j]; LU[k*3 + j] = LU[p*3 + j]; LU[p*3 + j] = t;
            }
            int t = perm[k]; perm[k] = perm[p]; perm[p] = t;
        }
        float rkk = __fdiv_rn(1.0f, LU[k*3 + k]);
        #pragma unroll
        for (int i = k + 1; i < 3; i++) {
            float l = __fmul_rn(LU[i*3 + k], rkk);
            LU[i*3 + k] = l;
            #pragma unroll
            for (int j = k + 1; j < 3; j++)
                LU[i*3 + j] = __fadd_rn(LU[i*3 + j], -__fmul_rn(l, LU[k*3 + j]));
        }
    }
    float r0 = __fdiv_rn(1.0f, LU[0]);
    float r1 = __fdiv_rn(1.0f, LU[4]);
    float r2 = __fdiv_rn(1.0f, LU[8]);
    #pragma unroll
    for (int c = 0; c < 3; c++) {
        float y0 = (perm[0] == c) ? 1.0f : 0.0f;
        float y1 = (perm[1] == c) ? 1.0f : 0.0f;
        float y2 = (perm[2] == c) ? 1.0f : 0.0f;
        y1 = __fadd_rn(y1, -__fmul_rn(LU[3], y0));
        y2 = __fadd_rn(y2, -__fmul_rn(LU[6], y0));
        y2 = __fadd_rn(y2, -__fmul_rn(LU[7], y1));
        float x2 = __fmul_rn(y2, r2);
        float x1 = __fmul_rn(__fadd_rn(y1, -__fmul_rn(LU[5], x2)), r1);
        float x0 = __fmul_rn(__fadd_rn(__fadd_rn(y0, -__fmul_rn(LU[1], x1)),
                                       -__fmul_rn(LU[2], x2)), r0);
        o[0*3 + c] = x0; o[1*3 + c] = x1; o[2*3 + c] = x2;
    }
}

// Zero the OUTPUT buffer (poisoned 0xAA; untouched voxels must be 0) and
// compute the per-camera matrices in block 0. The zero also installs the out
// lines in L2 so the splat's REDs hit dirty L2 lines.
__global__ void __launch_bounds__(256) zero_setup_kernel(
        float* __restrict__ out,
        const float* __restrict__ rots,
        const float* __restrict__ trans,
        const float* __restrict__ intrins,
        const float* __restrict__ post_rots,
        const float* __restrict__ post_trans) {
    float4* o4 = reinterpret_cast<float4*>(out);
    int base = blockIdx.x * 256 + threadIdx.x;
    const int stride = 3600 * 256;     // grid is 3600 blocks; 4*stride = OUT_ELEMS_/4
    #pragma unroll
    for (int i = 0; i < 4; i++)
        o4[base + i * stride] = make_float4(0.f, 0.f, 0.f, 0.f);

    if (blockIdx.x != 0) return;
    int i = threadIdx.x;
    if (i < FW_)   // numpy linspace: f64 w*step, endpoint override
        g_utab[i] = (i == FW_-1) ? 703.0f : (float)((double)i * (703.0 / 43.0));
    if (i >= B_*N_) return;
    float A[9], iK[9], ipr[9], R[9];
    #pragma unroll
    for (int k = 0; k < 9; k++) A[k] = intrins[i*9 + k];
    inv3x3_cublas_f32(A, iK);
    #pragma unroll
    for (int k = 0; k < 9; k++) A[k] = post_rots[i*9 + k];
    inv3x3_cublas_f32(A, ipr);
    #pragma unroll
    for (int k = 0; k < 9; k++) R[k] = rots[i*9 + k];

    float* M = g_mats[i];
    #pragma unroll
    for (int k = 0; k < 9; k++) M[k] = ipr[k];
    #pragma unroll
    for (int r = 0; r < 3; r++)
        #pragma unroll
        for (int c = 0; c < 3; c++)
            M[9 + r*3 + c] = dot3(R[r*3+0], R[r*3+1], R[r*3+2],
                                  iK[c], iK[3+c], iK[6+c]);
    M[18] = trans[i*3+0];      M[19] = trans[i*3+1];      M[20] = trans[i*3+2];
    M[21] = post_trans[i*3+0]; M[22] = post_trans[i*3+1]; M[23] = post_trans[i*3+2];
}

__device__ __forceinline__ void red_add_f32(float* p, float v) {
    asm volatile("red.global.add.f32 [%0], %1;" :: "l"(p), "f"(v) : "memory");
}

// Splat directly into the channel-major output.
// h-fastest mapping: the 16 points of a group (fixed b,n,d,w; h=0..15) usually
// share one voxel. Phase 1 computes each point's out-base bit-identically;
// phase 2: per unique lin in the group, presum the matching features and issue
// 4 scalar REDs per thread (thread = channel quad). Uniform groups take the
// fast path (16-feature presum, no scanning).
__global__ void __launch_bounds__(256) splat_kernel(const float* __restrict__ x,
                                                    float* __restrict__ out) {
    __shared__ int s_lin[256];   // b*C*NSPAT + s, or -1
    __shared__ int s_p[256];     // original point index (for x addressing)
    __shared__ int s_uni[16];
    int tid = threadIdx.x;
    int q = blockIdx.x * 256 + tid;

    // ---- phase 1: geometry (bit-identical arithmetic; h-fastest mapping) ----
    {
        int h = q & 15;            // FH_ == 16
        int t = q >> 4;
        int w = t % FW_;  t /= FW_;
        int d = t % D_;
        int bn = t / D_;           // b*N + n
        int b  = bn >> 2;          // N_ == 4
        s_p[tid] = ((bn * D_ + d) * FH_ + h) * FW_ + w;
        const float* M = g_mats[bn];

        float u   = g_utab[w];
        float v   = (float)(h * 17);            // 255/15 == 17 exact
        float dep = 4.0f + (float)d;

        float p0 = __fadd_rn(u,   -M[21]);
        float p1 = __fadd_rn(v,   -M[22]);
        float p2 = __fadd_rn(dep, -M[23]);
        float a0 = dot3(M[0], M[1], M[2], p0, p1, p2);
        float a1 = dot3(M[3], M[4], M[5], p0, p1, p2);
        float a2 = dot3(M[6], M[7], M[8], p0, p1, p2);
        float X = __fmul_rn(a0, a2);
        float Y = __fmul_rn(a1, a2);
        float Z = a2;
        float qx = __fadd_rn(dot3(M[ 9], M[10], M[11], X, Y, Z), M[18]);
        float qy = __fadd_rn(dot3(M[12], M[13], M[14], X, Y, Z), M[19]);
        float qz = __fadd_rn(dot3(M[15], M[16], M[17], X, Y, Z), M[20]);

        int vx = (int)__fdiv_rn(__fadd_rn(qx, 48.0f), 0.4f);
        int vy = (int)__fdiv_rn(__fadd_rn(qy, 48.0f), 0.4f);
        int vz = (int)__fdiv_rn(__fadd_rn(qz, 10.0f), 20.0f);
        bool kept = (vx >= 0) & (vx < NX_) & (vy >= 0) & (vy < NY_) & (vz == 0);
        s_lin[tid] = kept ? (b * (C_*NSPAT_) + vy * NX_ + vx) : -1;
    }
    __syncthreads();

    if ((tid & 15) == 0) {       // group-uniformity check (one thread per group)
        int g16 = tid;
        int l0 = s_lin[g16];
        bool uni = true;
        #pragma unroll
        for (int i = 1; i < 16; i++) uni &= (s_lin[g16 + i] == l0);
        s_uni[tid >> 4] = uni;
    }
    __syncthreads();

    // ---- phase 2: group per 16 threads; thread cq handles channels cq*4..+3 ----
    int g  = tid >> 4;
    int cq = tid & 15;
    const float4* x4 = reinterpret_cast<const float4*>(x);
    if (s_uni[g]) {
        int lin = s_lin[g * 16];
        if (lin >= 0) {
            float4 acc = __ldg(x4 + (size_t)s_p[g*16] * 16 + cq);
            #pragma unroll
            for (int i = 1; i < 16; i++) {
                float4 f = __ldg(x4 + (size_t)s_p[g*16 + i] * 16 + cq);
                acc.x = __fadd_rn(acc.x, f.x);
                acc.y = __fadd_rn(acc.y, f.y);
                acc.z = __fadd_rn(acc.z, f.z);
                acc.w = __fadd_rn(acc.w, f.w);
            }
            float* dst = out + (size_t)lin + (size_t)(cq*4) * NSPAT_;
            red_add_f32(dst + 0*NSPAT_, acc.x);
            red_add_f32(dst + 1*NSPAT_, acc.y);
            red_add_f32(dst + 2*NSPAT_, acc.z);
            red_add_f32(dst + 3*NSPAT_, acc.w);
        }
    } else {
        // generic: per unique lin, presum its subset, then 4 scalar REDs
        #pragma unroll 1
        for (int i = 0; i < 16; i++) {
            int li = s_lin[g*16 + i];
            if (li < 0) continue;
            bool first = true;
            #pragma unroll 1
            for (int j = 0; j < i; j++)
                if (s_lin[g*16 + j] == li) { first = false; break; }
            if (!first) continue;
            float4 acc = __ldg(x4 + (size_t)s_p[g*16 + i] * 16 + cq);
            #pragma unroll 1
            for (int j = i + 1; j < 16; j++) {
                if (s_lin[g*16 + j] == li) {
                    float4 f = __ldg(x4 + (size_t)s_p[g*16 + j] * 16 + cq);
                    acc.x = __fadd_rn(acc.x, f.x);
                    acc.y = __fadd_rn(acc.y, f.y);
                    acc.z = __fadd_rn(acc.z, f.z);
                    acc.w = __fadd_rn(acc.w, f.w);
                }
            }
            float* dst = out + (size_t)li + (size_t)(cq*4) * NSPAT_;
            red_add_f32(dst + 0*NSPAT_, acc.x);
            red_add_f32(dst + 1*NSPAT_, acc.y);
            red_add_f32(dst + 2*NSPAT_, acc.z);
            red_add_f32(dst + 3*NSPAT_, acc.w);
        }
    }
}

extern "C" void kernel_launch(void* const* d_in, const int* in_sizes, int n_in,
                              void* d_out, int out_size) {
    const float* x          = (const float*)d_in[0];
    const float* rots       = (const float*)d_in[1];
    const float* trans      = (const float*)d_in[2];
    const float* intrins    = (const float*)d_in[3];
    const float* post_rots  = (const float*)d_in[4];
    const float* post_trans = (const float*)d_in[5];
    float* out = (float*)d_out;

    zero_setup_kernel<<<3600, 256>>>(out, rots, trans, intrins, post_rots, post_trans);
    splat_kernel<<<NPTS_/256, 256>>>(x, out);
}